// round 15
// baseline (speedup 1.0000x reference)
#include <cuda_runtime.h>
#include <cuda_fp16.h>
#include <cstdint>
#include <math.h>

// Problem constants
#define L_SEQ   2048
#define N_BATCH 4
#define EMB     1024
#define NH      16
#define DH      64
#define NHEADS  (N_BATCH * NH)      // 64
#define M_ROWS  (L_SEQ * N_BATCH)   // 8192

// Q pre-scale: Dh^-0.5 * log2(e)  (softmax runs in log2 domain)
#define Q_SCALE 0.18033688011112042f

// ---------------------------------------------------------------------------
// Scratch (allocation-free: __device__ globals) — fp16 single-pass path
// ---------------------------------------------------------------------------
__device__ __half g_q16[(size_t)NHEADS * L_SEQ * DH];
__device__ __half g_k16[(size_t)NHEADS * L_SEQ * DH];
__device__ __half g_v16[(size_t)NHEADS * L_SEQ * DH];
__device__ __half g_x16[(size_t)M_ROWS * EMB];
__device__ __half g_wqkv16[(size_t)3 * EMB * EMB];
__device__ __half g_wout16[(size_t)EMB * EMB];
__device__ __half g_ctx16[(size_t)M_ROWS * EMB];

// ---------------------------------------------------------------------------
// PTX helpers (portable ISA: cp.async / ldmatrix / mma.sync)
// ---------------------------------------------------------------------------
__device__ __forceinline__ uint32_t smem_u32(const void* p) {
    uint32_t a;
    asm("{ .reg .u64 t; cvta.to.shared.u64 t, %1; cvt.u32.u64 %0, t; }"
        : "=r"(a) : "l"(p));
    return a;
}

#define SWZ128(o) ((o) ^ (((o) >> 3) & 0x70))

#define CP_ASYNC16(dst, src) \
    asm volatile("cp.async.cg.shared.global [%0], [%1], 16;" \
                 :: "r"(dst), "l"(src) : "memory")
#define CP_ASYNC_COMMIT()  asm volatile("cp.async.commit_group;" ::: "memory")
#define CP_ASYNC_WAIT(n)   asm volatile("cp.async.wait_group %0;" :: "n"(n) : "memory")

#define LDSM_X4(r0, r1, r2, r3, addr) \
    asm volatile("ldmatrix.sync.aligned.m8n8.x4.shared.b16 {%0,%1,%2,%3}, [%4];" \
                 : "=r"(r0), "=r"(r1), "=r"(r2), "=r"(r3) : "r"(addr))

#define LDSM_X4T(r0, r1, r2, r3, addr) \
    asm volatile("ldmatrix.sync.aligned.m8n8.x4.trans.shared.b16 {%0,%1,%2,%3}, [%4];" \
                 : "=r"(r0), "=r"(r1), "=r"(r2), "=r"(r3) : "r"(addr))

#define MMA_F16(c, a, b0, b1) \
    asm volatile("mma.sync.aligned.m16n8k16.row.col.f32.f16.f16.f32 " \
                 "{%0,%1,%2,%3}, {%4,%5,%6,%7}, {%8,%9}, {%0,%1,%2,%3};" \
                 : "+f"((c)[0]), "+f"((c)[1]), "+f"((c)[2]), "+f"((c)[3]) \
                 : "r"((a)[0]), "r"((a)[1]), "r"((a)[2]), "r"((a)[3]), \
                   "r"(b0), "r"(b1))

#define HALF2_ONES 0x3C003C00u   // {1.0h, 1.0h}

__device__ __forceinline__ uint32_t pack2h(float f0, float f1) {
    __half2 h = __floats2half2_rn(f0, f1);
    return *reinterpret_cast<uint32_t*>(&h);
}

// exp2 of two fp32 values -> packed fp16x2 (one MUFU op for both)
__device__ __forceinline__ uint32_t exp2_h2(float f0, float f1) {
    uint32_t r;
    asm("{\n\t.reg .b32 t;\n\t"
        "cvt.rn.f16x2.f32 t, %2, %1;\n\t"
        "ex2.approx.f16x2 %0, t;\n\t}"
        : "=r"(r) : "f"(f0), "f"(f1));
    return r;
}

// ---------------------------------------------------------------------------
// Kernel 0: fused vectorized fp32 -> fp16 quantize of x, wqkv, wout
// ---------------------------------------------------------------------------
#define N_X   (M_ROWS * EMB)
#define N_WQ  (3 * EMB * EMB)
#define N_WO  (EMB * EMB)
#define N_ALL4 ((N_X + N_WQ + N_WO) / 4)

__global__ __launch_bounds__(256) void quant_all_kernel(
    const float* __restrict__ x, const float* __restrict__ wqkv,
    const float* __restrict__ wout)
{
    for (int i = blockIdx.x * blockDim.x + threadIdx.x; i < N_ALL4;
         i += gridDim.x * blockDim.x) {
        const int base = i * 4;
        const float* src;
        __half* dst;
        int off;
        if (base < N_X)             { src = x;    dst = g_x16;    off = base; }
        else if (base < N_X + N_WQ) { src = wqkv; dst = g_wqkv16; off = base - N_X; }
        else                        { src = wout; dst = g_wout16; off = base - N_X - N_WQ; }
        float4 v = *(const float4*)(src + off);
        uint2 h;
        h.x = pack2h(v.x, v.y);
        h.y = pack2h(v.z, v.w);
        *(uint2*)(dst + off) = h;
    }
}

// ---------------------------------------------------------------------------
// HMMA GEMM (fp16): C[m, o] = sum_k A[m,k] * B[o,k]   (exact R8 structure)
// CTA 128x128, K-chunk 64, 3-stage cp.async pipeline, warp tile 32x64,
// 2 CTAs/SM. mode 0: QKV scatter epilogue; mode 1: fp32 out rows
// ---------------------------------------------------------------------------
#define TILE_B 16384
#define STAGE_B (2 * TILE_B)
#define GEMM_STAGES 3
#define GEMM_SMEM_BYTES (GEMM_STAGES * STAGE_B)   // 96 KB

__device__ __forceinline__ void gemm_load_stage(
    uint32_t smst, const __half* A, const __half* B,
    int arow0, int brow0, int k0, int tid)
{
#pragma unroll
    for (int r = 0; r < 4; r++) {
        const int idx = r * 256 + tid;
        const int row = idx >> 3;
        const int cc = idx & 7;
        const uint32_t off = SWZ128((uint32_t)(row * 128 + cc * 16));
        CP_ASYNC16(smst + off, A + (size_t)(arow0 + row) * EMB + k0 + cc * 8);
        CP_ASYNC16(smst + TILE_B + off,
                   B + (size_t)(brow0 + row) * EMB + k0 + cc * 8);
    }
    CP_ASYNC_COMMIT();
}

__global__ __launch_bounds__(256, 2) void tc_gemm_kernel(
    const __half* __restrict__ A, const __half* __restrict__ B,
    float* __restrict__ out, int mode)
{
    extern __shared__ __align__(1024) char sm[];
    const uint32_t smb = smem_u32(sm);

    const int tid = threadIdx.x;
    const int wid = tid >> 5;
    const int lane = tid & 31;
    const int warp_m = wid & 3;
    const int warp_n = wid >> 2;
    const int bx = blockIdx.x;
    const int by = blockIdx.y;

    float c[2][8][4];
#pragma unroll
    for (int mt = 0; mt < 2; mt++)
#pragma unroll
        for (int nt = 0; nt < 8; nt++)
#pragma unroll
            for (int i = 0; i < 4; i++) c[mt][nt][i] = 0.0f;

    const int a_row = lane & 15;
    const int a_cb  = (lane >> 4) * 16;
    const int b_row = (lane & 7) + ((lane >> 4) << 3);
    const int b_cb  = ((lane >> 3) & 1) * 16;

    const int NCHUNK = EMB / 64;
    gemm_load_stage(smb, A, B, by * 128, bx * 128, 0, tid);
    gemm_load_stage(smb + STAGE_B, A, B, by * 128, bx * 128, 64, tid);

    for (int ck = 0; ck < NCHUNK; ck++) {
        if (ck + 1 < NCHUNK) { CP_ASYNC_WAIT(1); } else { CP_ASYNC_WAIT(0); }
        __syncthreads();
        if (ck + 2 < NCHUNK)
            gemm_load_stage(smb + ((ck + 2) % GEMM_STAGES) * STAGE_B, A, B,
                            by * 128, bx * 128, (ck + 2) * 64, tid);

        const uint32_t smA = smb + (ck % GEMM_STAGES) * STAGE_B;
        const uint32_t smB = smA + TILE_B;

#pragma unroll
        for (int ks = 0; ks < 4; ks++) {
            const int kbyte = ks * 32;
            uint32_t a[2][4];
#pragma unroll
            for (int mt = 0; mt < 2; mt++) {
                const uint32_t off = SWZ128(
                    (uint32_t)((warp_m * 32 + mt * 16 + a_row) * 128 + kbyte + a_cb));
                LDSM_X4(a[mt][0], a[mt][1], a[mt][2], a[mt][3], smA + off);
            }
#pragma unroll
            for (int np = 0; np < 4; np++) {
                const uint32_t off = SWZ128(
                    (uint32_t)((warp_n * 64 + np * 16 + b_row) * 128 + kbyte + b_cb));
                uint32_t bh[4];
                LDSM_X4(bh[0], bh[1], bh[2], bh[3], smB + off);
#pragma unroll
                for (int mt = 0; mt < 2; mt++) {
                    MMA_F16(c[mt][2 * np],     a[mt], bh[0], bh[1]);
                    MMA_F16(c[mt][2 * np + 1], a[mt], bh[2], bh[3]);
                }
            }
        }
    }

    // ---- epilogue ----
    const int mrow_base = by * 128 + warp_m * 32 + (lane >> 2);
    const int ncol_base = warp_n * 64 + 2 * (lane & 3);
#pragma unroll
    for (int mt = 0; mt < 2; mt++) {
#pragma unroll
        for (int half = 0; half < 2; half++) {
            const int m = mrow_base + mt * 16 + half * 8;
            if (mode == 0) {
                const int l = m >> 2;
                const int nb = m & 3;
                const int sec = bx >> 3;      // 0=q 1=k 2=v
#pragma unroll
                for (int nt = 0; nt < 8; nt++) {
                    const int o = bx * 128 + ncol_base + nt * 8;
                    const int h = (o & 1023) >> 6;
                    const int d = o & 63;
                    const size_t idx =
                        ((size_t)(nb * NH + h) * L_SEQ + l) * DH + d;
                    float v0 = c[mt][nt][half * 2];
                    float v1 = c[mt][nt][half * 2 + 1];
                    if (sec == 0) {
                        v0 *= Q_SCALE; v1 *= Q_SCALE;
                        *(uint32_t*)(g_q16 + idx) = pack2h(v0, v1);
                    } else if (sec == 1) {
                        *(uint32_t*)(g_k16 + idx) = pack2h(v0, v1);
                    } else {
                        *(uint32_t*)(g_v16 + idx) = pack2h(v0, v1);
                    }
                }
            } else {
                float* row = out + (size_t)m * EMB + bx * 128 + ncol_base;
#pragma unroll
                for (int nt = 0; nt < 8; nt++) {
                    float2 v = make_float2(c[mt][nt][half * 2],
                                           c[mt][nt][half * 2 + 1]);
                    *(float2*)(row + nt * 8) = v;
                }
            }
        }
    }
}

// ---------------------------------------------------------------------------
// Kernel 2: causal flash attention on fp16 HMMA.
// CTA = (head, 256 q rows), 16 warps (512 threads), 64-key tiles, 3-stage
// pipeline, 2 CTAs/SM. Halves K/V L2 re-read traffic vs 128-row tiles.
// Warp-vote correction skip: bit-exact (skipped only when corr == 1.0).
// ---------------------------------------------------------------------------
#define AT_TILE 8192
#define AT_STAGE (2 * AT_TILE)
#define AT_STAGES 3
#define ATTN_SMEM_BYTES (AT_STAGES * AT_STAGE)   // 48 KB
#define AT_THREADS 512

__device__ __forceinline__ void attn_load_stage(
    uint32_t smst, const __half* K, const __half* V, int kbase, int tid)
{
    // 512 threads cover the 64x128B tile in one pass each for K and V
    const int row = tid >> 3;
    const int cc = tid & 7;
    const uint32_t off = SWZ128((uint32_t)(row * 128 + cc * 16));
    CP_ASYNC16(smst + off, K + (size_t)(kbase + row) * DH + cc * 8);
    CP_ASYNC16(smst + AT_TILE + off,
               V + (size_t)(kbase + row) * DH + cc * 8);
    CP_ASYNC_COMMIT();
}

__global__ __launch_bounds__(AT_THREADS, 2) void attn_hmma_kernel()
{
    extern __shared__ __align__(1024) char sm[];
    const uint32_t smb = smem_u32(sm);

    const int tid = threadIdx.x;
    const int wid = tid >> 5;                    // 0..15
    const int lane = tid & 31;
    const int head = blockIdx.x;
    const int bqt  = (int)gridDim.y - 1 - (int)blockIdx.y;  // heaviest first
    const int qbase = bqt * 256;

    const size_t hoff = (size_t)head * L_SEQ * DH;
    const __half* Q = g_q16 + hoff;
    const __half* K = g_k16 + hoff;
    const __half* V = g_v16 + hoff;

    const int r0 = qbase + wid * 16 + (lane >> 2);
    uint32_t qh[4][4];
#pragma unroll
    for (int kc = 0; kc < 4; kc++) {
        const int d0 = kc * 16 + 2 * (lane & 3);
        qh[kc][0] = *(const uint32_t*)(Q + (size_t)r0 * DH + d0);
        qh[kc][1] = *(const uint32_t*)(Q + (size_t)(r0 + 8) * DH + d0);
        qh[kc][2] = *(const uint32_t*)(Q + (size_t)r0 * DH + d0 + 8);
        qh[kc][3] = *(const uint32_t*)(Q + (size_t)(r0 + 8) * DH + d0 + 8);
    }

    float o[8][4];
#pragma unroll
    for (int t = 0; t < 8; t++)
#pragma unroll
        for (int i = 0; i < 4; i++) o[t][i] = 0.0f;
    float ol[4] = {0.0f, 0.0f, 0.0f, 0.0f};
    float m0 = -1e30f, m1 = -1e30f;

    const int b_row = (lane & 7) + ((lane >> 4) << 3);
    const int b_cb  = ((lane >> 3) & 1) * 16;
    const int v_row = ((lane >> 3) & 1) * 8 + (lane & 7);
    const int v_cb  = ((lane >> 4) & 1) * 16;

    const int nkt = qbase / 64 + 4;
    attn_load_stage(smb, K, V, 0, tid);
    attn_load_stage(smb + AT_STAGE, K, V, 64, tid);

    for (int kt = 0; kt < nkt; kt++) {
        if (kt + 1 < nkt) { CP_ASYNC_WAIT(1); } else { CP_ASYNC_WAIT(0); }
        __syncthreads();
        if (kt + 2 < nkt)
            attn_load_stage(smb + ((kt + 2) % AT_STAGES) * AT_STAGE,
                            K, V, (kt + 2) * 64, tid);

        const uint32_t sK = smb + (kt % AT_STAGES) * AT_STAGE;
        const uint32_t sV = sK + AT_TILE;

        // ---- S = Q K^T (log2 domain) ----
        float c[8][4];
#pragma unroll
        for (int t = 0; t < 8; t++)
#pragma unroll
            for (int i = 0; i < 4; i++) c[t][i] = 0.0f;

#pragma unroll
        for (int ng = 0; ng < 4; ng++) {
#pragma unroll
            for (int kc = 0; kc < 4; kc++) {
                const uint32_t off = SWZ128(
                    (uint32_t)((ng * 16 + b_row) * 128 + kc * 32 + b_cb));
                uint32_t bh[4];
                LDSM_X4(bh[0], bh[1], bh[2], bh[3], sK + off);
                MMA_F16(c[2 * ng],     qh[kc], bh[0], bh[1]);
                MMA_F16(c[2 * ng + 1], qh[kc], bh[2], bh[3]);
            }
        }

        // ---- causal mask (boundary tiles only) ----
        const int kb = kt * 64;
        if (kb + 63 > r0) {
#pragma unroll
            for (int t = 0; t < 8; t++) {
                const int col = kb + t * 8 + 2 * (lane & 3);
                if (col > r0)         c[t][0] = -1e30f;
                if (col + 1 > r0)     c[t][1] = -1e30f;
                if (col > r0 + 8)     c[t][2] = -1e30f;
                if (col + 1 > r0 + 8) c[t][3] = -1e30f;
            }
        }

        // ---- online softmax (log2 domain) ----
        float mx0 = -1e30f, mx1 = -1e30f;
#pragma unroll
        for (int t = 0; t < 8; t++) {
            mx0 = fmaxf(mx0, fmaxf(c[t][0], c[t][1]));
            mx1 = fmaxf(mx1, fmaxf(c[t][2], c[t][3]));
        }
        mx0 = fmaxf(mx0, __shfl_xor_sync(0xffffffffu, mx0, 1));
        mx0 = fmaxf(mx0, __shfl_xor_sync(0xffffffffu, mx0, 2));
        mx1 = fmaxf(mx1, __shfl_xor_sync(0xffffffffu, mx1, 1));
        mx1 = fmaxf(mx1, __shfl_xor_sync(0xffffffffu, mx1, 2));

        const float mn0 = fmaxf(m0, mx0);
        const float mn1 = fmaxf(m1, mx1);

        // Correction skip: if no lane's max advanced, corr == 1.0 exactly
        // and the rescale is the identity (bit-exact skip).
        const bool need = (mx0 > m0) || (mx1 > m1);
        if (__any_sync(0xffffffffu, need)) {
            const float corr0 = exp2f(m0 - mn0);
            const float corr1 = exp2f(m1 - mn1);
#pragma unroll
            for (int t = 0; t < 8; t++) {
                o[t][0] *= corr0; o[t][1] *= corr0;
                o[t][2] *= corr1; o[t][3] *= corr1;
            }
            ol[0] *= corr0; ol[1] *= corr0;
            ol[2] *= corr1; ol[3] *= corr1;
            m0 = mn0; m1 = mn1;
        }

        uint32_t ph[4][4];
#pragma unroll
        for (int kc = 0; kc < 4; kc++) {
            ph[kc][0] = exp2_h2(c[2 * kc][0] - m0,     c[2 * kc][1] - m0);
            ph[kc][1] = exp2_h2(c[2 * kc][2] - m1,     c[2 * kc][3] - m1);
            ph[kc][2] = exp2_h2(c[2 * kc + 1][0] - m0, c[2 * kc + 1][1] - m0);
            ph[kc][3] = exp2_h2(c[2 * kc + 1][2] - m1, c[2 * kc + 1][3] - m1);
        }

        // ---- O += P V; l += P @ ones ----
#pragma unroll
        for (int kc = 0; kc < 4; kc++) {
#pragma unroll
            for (int ng = 0; ng < 4; ng++) {
                const uint32_t off = SWZ128(
                    (uint32_t)((kc * 16 + v_row) * 128 + ng * 32 + v_cb));
                uint32_t vh[4];
                LDSM_X4T(vh[0], vh[1], vh[2], vh[3], sV + off);
                MMA_F16(o[2 * ng],     ph[kc], vh[0], vh[1]);
                MMA_F16(o[2 * ng + 1], ph[kc], vh[2], vh[3]);
            }
            MMA_F16(ol, ph[kc], HALF2_ONES, HALF2_ONES);
        }
    }

    // ---- epilogue: normalize, fp16 ctx [L][N][E] ----
    const float inv0 = 1.0f / ol[0];
    const float inv1 = 1.0f / ol[2];
    const int nb = head >> 4;
    const int hh = head & 15;
    const size_t base0 =
        ((size_t)r0 * N_BATCH + nb) * EMB + hh * DH + 2 * (lane & 3);
    const size_t base1 = base0 + (size_t)8 * N_BATCH * EMB;
#pragma unroll
    for (int t = 0; t < 8; t++) {
        *(uint32_t*)(g_ctx16 + base0 + t * 8) =
            pack2h(o[t][0] * inv0, o[t][1] * inv0);
        *(uint32_t*)(g_ctx16 + base1 + t * 8) =
            pack2h(o[t][2] * inv1, o[t][3] * inv1);
    }
}

// ---------------------------------------------------------------------------
extern "C" void kernel_launch(void* const* d_in, const int* in_sizes, int n_in,
                              void* d_out, int out_size)
{
    const float* x    = (const float*)d_in[0];
    const float* wqkv = (const float*)d_in[1];
    const float* wout = (const float*)d_in[2];
    float* out = (float*)d_out;

    cudaFuncSetAttribute(tc_gemm_kernel,
                         cudaFuncAttributeMaxDynamicSharedMemorySize,
                         GEMM_SMEM_BYTES);
    cudaFuncSetAttribute(attn_hmma_kernel,
                         cudaFuncAttributeMaxDynamicSharedMemorySize,
                         ATTN_SMEM_BYTES);

    __half *x16, *w16, *o16, *ctx16;
    cudaGetSymbolAddress((void**)&x16, g_x16);
    cudaGetSymbolAddress((void**)&w16, g_wqkv16);
    cudaGetSymbolAddress((void**)&o16, g_wout16);
    cudaGetSymbolAddress((void**)&ctx16, g_ctx16);

    quant_all_kernel<<<592, 256>>>(x, wqkv, wout);

    tc_gemm_kernel<<<dim3(24, 64), 256, GEMM_SMEM_BYTES>>>(
        x16, w16, nullptr, 0);

    // 256-row q-tiles: grid (heads, 8), 512 threads
    attn_hmma_kernel<<<dim3(64, 8), AT_THREADS, ATTN_SMEM_BYTES>>>();

    tc_gemm_kernel<<<dim3(8, 64), 256, GEMM_SMEM_BYTES>>>(
        ctx16, o16, out, 1);
}

// round 16
// speedup vs baseline: 1.7830x; 1.7830x over previous
#include <cuda_runtime.h>
#include <cuda_fp16.h>
#include <cstdint>
#include <math.h>

// Problem constants
#define L_SEQ   2048
#define N_BATCH 4
#define EMB     1024
#define NH      16
#define DH      64
#define NHEADS  (N_BATCH * NH)      // 64
#define M_ROWS  (L_SEQ * N_BATCH)   // 8192

// Q pre-scale: Dh^-0.5 * log2(e)  (softmax runs in log2 domain)
#define Q_SCALE 0.18033688011112042f

// ---------------------------------------------------------------------------
// Scratch (allocation-free: __device__ globals) — fp16 single-pass path
// ---------------------------------------------------------------------------
__device__ __half g_q16[(size_t)NHEADS * L_SEQ * DH];
__device__ __half g_k16[(size_t)NHEADS * L_SEQ * DH];
__device__ __half g_v16[(size_t)NHEADS * L_SEQ * DH];
__device__ __half g_x16[(size_t)M_ROWS * EMB];
__device__ __half g_wqkv16[(size_t)3 * EMB * EMB];
__device__ __half g_wout16[(size_t)EMB * EMB];
__device__ __half g_ctx16[(size_t)M_ROWS * EMB];

// ---------------------------------------------------------------------------
// PTX helpers (portable ISA: cp.async / ldmatrix / mma.sync)
// ---------------------------------------------------------------------------
__device__ __forceinline__ uint32_t smem_u32(const void* p) {
    uint32_t a;
    asm("{ .reg .u64 t; cvta.to.shared.u64 t, %1; cvt.u32.u64 %0, t; }"
        : "=r"(a) : "l"(p));
    return a;
}

#define SWZ128(o) ((o) ^ (((o) >> 3) & 0x70))

#define CP_ASYNC16(dst, src) \
    asm volatile("cp.async.cg.shared.global [%0], [%1], 16;" \
                 :: "r"(dst), "l"(src) : "memory")
#define CP_ASYNC_COMMIT()  asm volatile("cp.async.commit_group;" ::: "memory")
#define CP_ASYNC_WAIT(n)   asm volatile("cp.async.wait_group %0;" :: "n"(n) : "memory")

#define LDSM_X4(r0, r1, r2, r3, addr) \
    asm volatile("ldmatrix.sync.aligned.m8n8.x4.shared.b16 {%0,%1,%2,%3}, [%4];" \
                 : "=r"(r0), "=r"(r1), "=r"(r2), "=r"(r3) : "r"(addr))

#define LDSM_X4T(r0, r1, r2, r3, addr) \
    asm volatile("ldmatrix.sync.aligned.m8n8.x4.trans.shared.b16 {%0,%1,%2,%3}, [%4];" \
                 : "=r"(r0), "=r"(r1), "=r"(r2), "=r"(r3) : "r"(addr))

#define MMA_F16(c, a, b0, b1) \
    asm volatile("mma.sync.aligned.m16n8k16.row.col.f32.f16.f16.f32 " \
                 "{%0,%1,%2,%3}, {%4,%5,%6,%7}, {%8,%9}, {%0,%1,%2,%3};" \
                 : "+f"((c)[0]), "+f"((c)[1]), "+f"((c)[2]), "+f"((c)[3]) \
                 : "r"((a)[0]), "r"((a)[1]), "r"((a)[2]), "r"((a)[3]), \
                   "r"(b0), "r"(b1))

#define HALF2_ONES 0x3C003C00u   // {1.0h, 1.0h}

__device__ __forceinline__ uint32_t pack2h(float f0, float f1) {
    __half2 h = __floats2half2_rn(f0, f1);
    return *reinterpret_cast<uint32_t*>(&h);
}

// exp2 of two fp32 values -> packed fp16x2 (one MUFU op for both)
__device__ __forceinline__ uint32_t exp2_h2(float f0, float f1) {
    uint32_t r;
    asm("{\n\t.reg .b32 t;\n\t"
        "cvt.rn.f16x2.f32 t, %2, %1;\n\t"
        "ex2.approx.f16x2 %0, t;\n\t}"
        : "=r"(r) : "f"(f0), "f"(f1));
    return r;
}

// ---------------------------------------------------------------------------
// Kernel 0: fused vectorized fp32 -> fp16 quantize of x, wqkv, wout
// ---------------------------------------------------------------------------
#define N_X   (M_ROWS * EMB)
#define N_WQ  (3 * EMB * EMB)
#define N_WO  (EMB * EMB)
#define N_ALL4 ((N_X + N_WQ + N_WO) / 4)

__global__ __launch_bounds__(256) void quant_all_kernel(
    const float* __restrict__ x, const float* __restrict__ wqkv,
    const float* __restrict__ wout)
{
    for (int i = blockIdx.x * blockDim.x + threadIdx.x; i < N_ALL4;
         i += gridDim.x * blockDim.x) {
        const int base = i * 4;
        const float* src;
        __half* dst;
        int off;
        if (base < N_X)             { src = x;    dst = g_x16;    off = base; }
        else if (base < N_X + N_WQ) { src = wqkv; dst = g_wqkv16; off = base - N_X; }
        else                        { src = wout; dst = g_wout16; off = base - N_X - N_WQ; }
        float4 v = *(const float4*)(src + off);
        uint2 h;
        h.x = pack2h(v.x, v.y);
        h.y = pack2h(v.z, v.w);
        *(uint2*)(dst + off) = h;
    }
}

// ---------------------------------------------------------------------------
// HMMA GEMM (fp16): C[m, o] = sum_k A[m,k] * B[o,k]
// CTA 128x128, K-chunk 64, 3-stage cp.async pipeline, warp tile 32x64,
// 2 CTAs/SM (inter-CTA overlap hides prologue/epilogue drains).
// mode 0: QKV scatter epilogue (q scaled by Q_SCALE); mode 1: fp32 out rows
// ---------------------------------------------------------------------------
#define TILE_B 16384
#define STAGE_B (2 * TILE_B)
#define GEMM_STAGES 3
#define GEMM_SMEM_BYTES (GEMM_STAGES * STAGE_B)   // 96 KB

__device__ __forceinline__ void gemm_load_stage(
    uint32_t smst, const __half* A, const __half* B,
    int arow0, int brow0, int k0, int tid)
{
#pragma unroll
    for (int r = 0; r < 4; r++) {
        const int idx = r * 256 + tid;
        const int row = idx >> 3;
        const int cc = idx & 7;
        const uint32_t off = SWZ128((uint32_t)(row * 128 + cc * 16));
        CP_ASYNC16(smst + off, A + (size_t)(arow0 + row) * EMB + k0 + cc * 8);
        CP_ASYNC16(smst + TILE_B + off,
                   B + (size_t)(brow0 + row) * EMB + k0 + cc * 8);
    }
    CP_ASYNC_COMMIT();
}

__global__ __launch_bounds__(256, 2) void tc_gemm_kernel(
    const __half* __restrict__ A, const __half* __restrict__ B,
    float* __restrict__ out, int mode)
{
    extern __shared__ __align__(1024) char sm[];
    const uint32_t smb = smem_u32(sm);

    const int tid = threadIdx.x;
    const int wid = tid >> 5;
    const int lane = tid & 31;
    const int warp_m = wid & 3;
    const int warp_n = wid >> 2;
    const int bx = blockIdx.x;
    const int by = blockIdx.y;

    float c[2][8][4];
#pragma unroll
    for (int mt = 0; mt < 2; mt++)
#pragma unroll
        for (int nt = 0; nt < 8; nt++)
#pragma unroll
            for (int i = 0; i < 4; i++) c[mt][nt][i] = 0.0f;

    const int a_row = lane & 15;
    const int a_cb  = (lane >> 4) * 16;
    const int b_row = (lane & 7) + ((lane >> 4) << 3);
    const int b_cb  = ((lane >> 3) & 1) * 16;

    const int NCHUNK = EMB / 64;
    gemm_load_stage(smb, A, B, by * 128, bx * 128, 0, tid);
    gemm_load_stage(smb + STAGE_B, A, B, by * 128, bx * 128, 64, tid);

    for (int ck = 0; ck < NCHUNK; ck++) {
        if (ck + 1 < NCHUNK) { CP_ASYNC_WAIT(1); } else { CP_ASYNC_WAIT(0); }
        __syncthreads();
        if (ck + 2 < NCHUNK)
            gemm_load_stage(smb + ((ck + 2) % GEMM_STAGES) * STAGE_B, A, B,
                            by * 128, bx * 128, (ck + 2) * 64, tid);

        const uint32_t smA = smb + (ck % GEMM_STAGES) * STAGE_B;
        const uint32_t smB = smA + TILE_B;

#pragma unroll
        for (int ks = 0; ks < 4; ks++) {
            const int kbyte = ks * 32;
            uint32_t a[2][4];
#pragma unroll
            for (int mt = 0; mt < 2; mt++) {
                const uint32_t off = SWZ128(
                    (uint32_t)((warp_m * 32 + mt * 16 + a_row) * 128 + kbyte + a_cb));
                LDSM_X4(a[mt][0], a[mt][1], a[mt][2], a[mt][3], smA + off);
            }
#pragma unroll
            for (int np = 0; np < 4; np++) {
                const uint32_t off = SWZ128(
                    (uint32_t)((warp_n * 64 + np * 16 + b_row) * 128 + kbyte + b_cb));
                uint32_t bh[4];
                LDSM_X4(bh[0], bh[1], bh[2], bh[3], smB + off);
#pragma unroll
                for (int mt = 0; mt < 2; mt++) {
                    MMA_F16(c[mt][2 * np],     a[mt], bh[0], bh[1]);
                    MMA_F16(c[mt][2 * np + 1], a[mt], bh[2], bh[3]);
                }
            }
        }
    }

    // ---- epilogue ----
    const int mrow_base = by * 128 + warp_m * 32 + (lane >> 2);
    const int ncol_base = warp_n * 64 + 2 * (lane & 3);
#pragma unroll
    for (int mt = 0; mt < 2; mt++) {
#pragma unroll
        for (int half = 0; half < 2; half++) {
            const int m = mrow_base + mt * 16 + half * 8;
            if (mode == 0) {
                const int l = m >> 2;
                const int nb = m & 3;
                const int sec = bx >> 3;      // 0=q 1=k 2=v
#pragma unroll
                for (int nt = 0; nt < 8; nt++) {
                    const int o = bx * 128 + ncol_base + nt * 8;
                    const int h = (o & 1023) >> 6;
                    const int d = o & 63;
                    const size_t idx =
                        ((size_t)(nb * NH + h) * L_SEQ + l) * DH + d;
                    float v0 = c[mt][nt][half * 2];
                    float v1 = c[mt][nt][half * 2 + 1];
                    if (sec == 0) {
                        v0 *= Q_SCALE; v1 *= Q_SCALE;
                        *(uint32_t*)(g_q16 + idx) = pack2h(v0, v1);
                    } else if (sec == 1) {
                        *(uint32_t*)(g_k16 + idx) = pack2h(v0, v1);
                    } else {
                        *(uint32_t*)(g_v16 + idx) = pack2h(v0, v1);
                    }
                }
            } else {
                float* row = out + (size_t)m * EMB + bx * 128 + ncol_base;
#pragma unroll
                for (int nt = 0; nt < 8; nt++) {
                    float2 v = make_float2(c[mt][nt][half * 2],
                                           c[mt][nt][half * 2 + 1]);
                    *(float2*)(row + nt * 8) = v;
                }
            }
        }
    }
}

// ---------------------------------------------------------------------------
// Kernel 2: causal flash attention on fp16 HMMA, log2-domain softmax with
// fp16x2 ex2 and ones-MMA row sums. CTA = (head, 128 q rows), 8 warps,
// 64-key tiles, 3-stage pipeline, heaviest q-tiles first.
// ---------------------------------------------------------------------------
#define AT_TILE 8192
#define AT_STAGE (2 * AT_TILE)
#define AT_STAGES 3
#define ATTN_SMEM_BYTES (AT_STAGES * AT_STAGE)   // 48 KB

__device__ __forceinline__ void attn_load_stage(
    uint32_t smst, const __half* K, const __half* V, int kbase, int tid)
{
#pragma unroll
    for (int it = 0; it < 2; it++) {
        const int idx = it * 256 + tid;
        const int row = idx >> 3;
        const int cc = idx & 7;
        const uint32_t off = SWZ128((uint32_t)(row * 128 + cc * 16));
        CP_ASYNC16(smst + off, K + (size_t)(kbase + row) * DH + cc * 8);
        CP_ASYNC16(smst + AT_TILE + off,
                   V + (size_t)(kbase + row) * DH + cc * 8);
    }
    CP_ASYNC_COMMIT();
}

__global__ __launch_bounds__(256, 2) void attn_hmma_kernel()
{
    extern __shared__ __align__(1024) char sm[];
    const uint32_t smb = smem_u32(sm);

    const int tid = threadIdx.x;
    const int wid = tid >> 5;
    const int lane = tid & 31;
    const int head = blockIdx.x;
    const int bqt  = (int)gridDim.y - 1 - (int)blockIdx.y;  // heaviest first
    const int qbase = bqt * 128;

    const size_t hoff = (size_t)head * L_SEQ * DH;
    const __half* Q = g_q16 + hoff;
    const __half* K = g_k16 + hoff;
    const __half* V = g_v16 + hoff;

    const int r0 = qbase + wid * 16 + (lane >> 2);
    uint32_t qh[4][4];
#pragma unroll
    for (int kc = 0; kc < 4; kc++) {
        const int d0 = kc * 16 + 2 * (lane & 3);
        qh[kc][0] = *(const uint32_t*)(Q + (size_t)r0 * DH + d0);
        qh[kc][1] = *(const uint32_t*)(Q + (size_t)(r0 + 8) * DH + d0);
        qh[kc][2] = *(const uint32_t*)(Q + (size_t)r0 * DH + d0 + 8);
        qh[kc][3] = *(const uint32_t*)(Q + (size_t)(r0 + 8) * DH + d0 + 8);
    }

    float o[8][4];
#pragma unroll
    for (int t = 0; t < 8; t++)
#pragma unroll
        for (int i = 0; i < 4; i++) o[t][i] = 0.0f;
    float ol[4] = {0.0f, 0.0f, 0.0f, 0.0f};
    float m0 = -1e30f, m1 = -1e30f;

    const int b_row = (lane & 7) + ((lane >> 4) << 3);
    const int b_cb  = ((lane >> 3) & 1) * 16;
    const int v_row = ((lane >> 3) & 1) * 8 + (lane & 7);
    const int v_cb  = ((lane >> 4) & 1) * 16;

    const int nkt = qbase / 64 + 2;
    attn_load_stage(smb, K, V, 0, tid);
    if (nkt > 1) attn_load_stage(smb + AT_STAGE, K, V, 64, tid);

    for (int kt = 0; kt < nkt; kt++) {
        if (kt + 1 < nkt) { CP_ASYNC_WAIT(1); } else { CP_ASYNC_WAIT(0); }
        __syncthreads();
        if (kt + 2 < nkt)
            attn_load_stage(smb + ((kt + 2) % AT_STAGES) * AT_STAGE,
                            K, V, (kt + 2) * 64, tid);

        const uint32_t sK = smb + (kt % AT_STAGES) * AT_STAGE;
        const uint32_t sV = sK + AT_TILE;

        // ---- S = Q K^T (log2 domain) ----
        float c[8][4];
#pragma unroll
        for (int t = 0; t < 8; t++)
#pragma unroll
            for (int i = 0; i < 4; i++) c[t][i] = 0.0f;

#pragma unroll
        for (int ng = 0; ng < 4; ng++) {
#pragma unroll
            for (int kc = 0; kc < 4; kc++) {
                const uint32_t off = SWZ128(
                    (uint32_t)((ng * 16 + b_row) * 128 + kc * 32 + b_cb));
                uint32_t bh[4];
                LDSM_X4(bh[0], bh[1], bh[2], bh[3], sK + off);
                MMA_F16(c[2 * ng],     qh[kc], bh[0], bh[1]);
                MMA_F16(c[2 * ng + 1], qh[kc], bh[2], bh[3]);
            }
        }

        // ---- causal mask (boundary tiles only) ----
        const int kb = kt * 64;
        if (kb + 63 > r0) {
#pragma unroll
            for (int t = 0; t < 8; t++) {
                const int col = kb + t * 8 + 2 * (lane & 3);
                if (col > r0)         c[t][0] = -1e30f;
                if (col + 1 > r0)     c[t][1] = -1e30f;
                if (col > r0 + 8)     c[t][2] = -1e30f;
                if (col + 1 > r0 + 8) c[t][3] = -1e30f;
            }
        }

        // ---- online softmax (log2 domain) ----
        float mx0 = -1e30f, mx1 = -1e30f;
#pragma unroll
        for (int t = 0; t < 8; t++) {
            mx0 = fmaxf(mx0, fmaxf(c[t][0], c[t][1]));
            mx1 = fmaxf(mx1, fmaxf(c[t][2], c[t][3]));
        }
        mx0 = fmaxf(mx0, __shfl_xor_sync(0xffffffffu, mx0, 1));
        mx0 = fmaxf(mx0, __shfl_xor_sync(0xffffffffu, mx0, 2));
        mx1 = fmaxf(mx1, __shfl_xor_sync(0xffffffffu, mx1, 1));
        mx1 = fmaxf(mx1, __shfl_xor_sync(0xffffffffu, mx1, 2));

        const float mn0 = fmaxf(m0, mx0);
        const float mn1 = fmaxf(m1, mx1);
        const float corr0 = exp2f(m0 - mn0);
        const float corr1 = exp2f(m1 - mn1);
        m0 = mn0; m1 = mn1;

        uint32_t ph[4][4];
#pragma unroll
        for (int kc = 0; kc < 4; kc++) {
            ph[kc][0] = exp2_h2(c[2 * kc][0] - mn0,     c[2 * kc][1] - mn0);
            ph[kc][1] = exp2_h2(c[2 * kc][2] - mn1,     c[2 * kc][3] - mn1);
            ph[kc][2] = exp2_h2(c[2 * kc + 1][0] - mn0, c[2 * kc + 1][1] - mn0);
            ph[kc][3] = exp2_h2(c[2 * kc + 1][2] - mn1, c[2 * kc + 1][3] - mn1);
        }

#pragma unroll
        for (int t = 0; t < 8; t++) {
            o[t][0] *= corr0; o[t][1] *= corr0;
            o[t][2] *= corr1; o[t][3] *= corr1;
        }
        ol[0] *= corr0; ol[1] *= corr0;
        ol[2] *= corr1; ol[3] *= corr1;

        // ---- O += P V; l += P @ ones ----
#pragma unroll
        for (int kc = 0; kc < 4; kc++) {
#pragma unroll
            for (int ng = 0; ng < 4; ng++) {
                const uint32_t off = SWZ128(
                    (uint32_t)((kc * 16 + v_row) * 128 + ng * 32 + v_cb));
                uint32_t vh[4];
                LDSM_X4T(vh[0], vh[1], vh[2], vh[3], sV + off);
                MMA_F16(o[2 * ng],     ph[kc], vh[0], vh[1]);
                MMA_F16(o[2 * ng + 1], ph[kc], vh[2], vh[3]);
            }
            MMA_F16(ol, ph[kc], HALF2_ONES, HALF2_ONES);
        }
    }

    // ---- epilogue ----
    const float inv0 = 1.0f / ol[0];
    const float inv1 = 1.0f / ol[2];
    const int nb = head >> 4;
    const int hh = head & 15;
    const size_t base0 =
        ((size_t)r0 * N_BATCH + nb) * EMB + hh * DH + 2 * (lane & 3);
    const size_t base1 = base0 + (size_t)8 * N_BATCH * EMB;
#pragma unroll
    for (int t = 0; t < 8; t++) {
        *(uint32_t*)(g_ctx16 + base0 + t * 8) =
            pack2h(o[t][0] * inv0, o[t][1] * inv0);
        *(uint32_t*)(g_ctx16 + base1 + t * 8) =
            pack2h(o[t][2] * inv1, o[t][3] * inv1);
    }
}

// ---------------------------------------------------------------------------
extern "C" void kernel_launch(void* const* d_in, const int* in_sizes, int n_in,
                              void* d_out, int out_size)
{
    const float* x    = (const float*)d_in[0];
    const float* wqkv = (const float*)d_in[1];
    const float* wout = (const float*)d_in[2];
    float* out = (float*)d_out;

    cudaFuncSetAttribute(tc_gemm_kernel,
                         cudaFuncAttributeMaxDynamicSharedMemorySize,
                         GEMM_SMEM_BYTES);
    cudaFuncSetAttribute(attn_hmma_kernel,
                         cudaFuncAttributeMaxDynamicSharedMemorySize,
                         ATTN_SMEM_BYTES);

    __half *x16, *w16, *o16, *ctx16;
    cudaGetSymbolAddress((void**)&x16, g_x16);
    cudaGetSymbolAddress((void**)&w16, g_wqkv16);
    cudaGetSymbolAddress((void**)&o16, g_wout16);
    cudaGetSymbolAddress((void**)&ctx16, g_ctx16);

    quant_all_kernel<<<592, 256>>>(x, wqkv, wout);

    tc_gemm_kernel<<<dim3(24, 64), 256, GEMM_SMEM_BYTES>>>(
        x16, w16, nullptr, 0);

    attn_hmma_kernel<<<dim3(64, 16), 256, ATTN_SMEM_BYTES>>>();

    tc_gemm_kernel<<<dim3(8, 64), 256, GEMM_SMEM_BYTES>>>(
        ctx16, o16, out, 1);
}